// round 10
// baseline (speedup 1.0000x reference)
#include <cuda_runtime.h>

#define NN 100000
#define DD 64
#define EMAX 800000
#define TOT (4 * NN)              // total count slots
#define NB ((TOT + 1023) / 1024)  // scan blocks = 391

// Scratch (static device globals; no runtime allocation).
// slot layout (by dst): 0=dd(drug) 1=gd(drug) 2=dg(gene) 3=gg(gene)
__device__ int g_cnt[TOT];           // per-(slot,dst) degree
__device__ int g_incl[TOT];          // block-inclusive scan
__device__ int g_base[TOT];          // exclusive offsets; after scatter_perm = end offsets
__device__ int g_bsum[512];          // per-block totals
__device__ int g_bbase[512];         // exclusive block bases
__device__ int g_psrc[4ull * EMAX];  // src indices sorted by (slot, dst)

// ---------------------------------------------------------------------------
// Zero degree counters (every launch: self-contained graph replays).
// ---------------------------------------------------------------------------
__global__ void zero_cnt_kernel() {
    int i = blockIdx.x * blockDim.x + threadIdx.x;
    if (i < TOT) g_cnt[i] = 0;
}

// ---------------------------------------------------------------------------
// Counting sort, step 1: per-(slot,dst) histogram.
// ---------------------------------------------------------------------------
__global__ __launch_bounds__(256) void hist_kernel(
    const int* __restrict__ dst0, const int* __restrict__ dst1,
    const int* __restrict__ dst2, const int* __restrict__ dst3,
    int n_edges) {
    int e = blockIdx.x * 256 + threadIdx.x;
    if (e >= n_edges) return;
    const int slot = blockIdx.y;
    const int* dst = (slot == 0) ? dst0 : (slot == 1) ? dst1 : (slot == 2) ? dst2 : dst3;
    atomicAdd(&g_cnt[slot * NN + __ldg(dst + e)], 1);
}

// ---------------------------------------------------------------------------
// Step 2a: per-block inclusive scan (1024 elems/block) + block totals.
// ---------------------------------------------------------------------------
__global__ __launch_bounds__(1024) void scan_blocks_kernel() {
    __shared__ int s[1024];
    const int tid = threadIdx.x;
    const int i = blockIdx.x * 1024 + tid;
    int v = (i < TOT) ? g_cnt[i] : 0;
    s[tid] = v;
    __syncthreads();
#pragma unroll
    for (int off = 1; off < 1024; off <<= 1) {
        int t = (tid >= off) ? s[tid - off] : 0;
        __syncthreads();
        s[tid] += t;
        __syncthreads();
    }
    if (i < TOT) g_incl[i] = s[tid];
    if (tid == 1023) g_bsum[blockIdx.x] = s[1023];
}

// Step 2b: scan the 391 block totals (single block) -> exclusive block bases.
__global__ __launch_bounds__(512) void scan_partials_kernel() {
    __shared__ int s[512];
    const int tid = threadIdx.x;
    int v = (tid < NB) ? g_bsum[tid] : 0;
    s[tid] = v;
    __syncthreads();
#pragma unroll
    for (int off = 1; off < 512; off <<= 1) {
        int t = (tid >= off) ? s[tid - off] : 0;
        __syncthreads();
        s[tid] += t;
        __syncthreads();
    }
    g_bbase[tid] = s[tid] - v;  // exclusive
}

// Step 2c: global exclusive offset per slot-index.
__global__ __launch_bounds__(256) void add_base_kernel() {
    int i = blockIdx.x * 256 + threadIdx.x;
    if (i >= TOT) return;
    g_base[i] = g_bbase[i >> 10] + g_incl[i] - g_cnt[i];
}

// ---------------------------------------------------------------------------
// Step 3: scatter src indices into dst-sorted order. Afterwards g_base[idx]
// holds the END offset of segment idx (start = end - g_cnt[idx]).
// ---------------------------------------------------------------------------
__global__ __launch_bounds__(256) void scatter_perm_kernel(
    const int* __restrict__ src0, const int* __restrict__ dst0,
    const int* __restrict__ src1, const int* __restrict__ dst1,
    const int* __restrict__ src2, const int* __restrict__ dst2,
    const int* __restrict__ src3, const int* __restrict__ dst3,
    int n_edges) {
    int e = blockIdx.x * 256 + threadIdx.x;
    if (e >= n_edges) return;
    const int slot = blockIdx.y;
    const int* src; const int* dst;
    switch (slot) {
        case 0:  src = src0; dst = dst0; break;
        case 1:  src = src1; dst = dst1; break;
        case 2:  src = src2; dst = dst2; break;
        default: src = src3; dst = dst3; break;
    }
    const int s = __ldg(src + e);
    const int d = __ldg(dst + e);
    int pos = atomicAdd(&g_base[slot * NN + d], 1);
    g_psrc[pos] = s;
}

// ---------------------------------------------------------------------------
// f32x2 packed-FMA helpers (Blackwell).
// ---------------------------------------------------------------------------
__device__ __forceinline__ unsigned long long pk2(float lo, float hi) {
    unsigned long long r;
    asm("mov.b64 %0, {%1, %2};" : "=l"(r) : "f"(lo), "f"(hi));
    return r;
}
__device__ __forceinline__ void fma2(unsigned long long& acc,
                                     unsigned long long a, unsigned long long b) {
    asm("fma.rn.f32x2 %0, %1, %2, %0;" : "+l"(acc) : "l"(a), "l"(b));
}
__device__ __forceinline__ float2 up2(unsigned long long v) {
    float2 f;
    asm("mov.b64 {%0, %1}, %2;" : "=f"(f.x), "=f"(f.y) : "l"(v));
    return f;
}

// ---------------------------------------------------------------------------
// Fused pull-gather + per-node 64x64 GEMM + bias + relu + output.
// Linearity: (sum_e x[src]) / deg @ W == GraphConv(norm='right').
// 16 lanes per node-group, 8 nodes per group. Aggregates staged in smem and
// broadcast via same-address LDS.128 (no shuffles). W loaded per-relation
// (16 KB) to stay under the 48 KB static smem cap. Lane l owns output cols
// [4l, 4l+4).
// ---------------------------------------------------------------------------
__global__ __launch_bounds__(256) void gather_gemm_kernel(
    const float* __restrict__ xd, const float* __restrict__ xg,
    const float* __restrict__ Wdd, const float* __restrict__ Wdg,
    const float* __restrict__ Wgd, const float* __restrict__ Wgg,
    const float* __restrict__ bias, float* __restrict__ out) {
    __shared__ float Wsm[64 * 64];  // 16 KB: [k*64 + c], current relation's W
    __shared__ float Asm[128][64];  // 32 KB: normalized aggregates, 128 nodes/block

    const int t = blockIdx.y;  // 0=drug dst, 1=gene dst
    const int tid = threadIdx.x;
    const int lane = tid & 15;
    const int group = tid >> 4;                      // 0..15
    const int node0 = blockIdx.x * 128 + group * 8;  // 8 nodes per group

    // rel0 src = x_drug, rel1 src = x_gene.
    //   t=0: rel0=(slot0, W_dd), rel1=(slot1, W_gd)
    //   t=1: rel0=(slot2, W_dg), rel1=(slot3, W_gg)
    const float* W0 = t ? Wdg : Wdd;
    const float* W1 = t ? Wgg : Wgd;

    unsigned long long res01[8], res23[8];
    const unsigned long long z = pk2(0.f, 0.f);
#pragma unroll
    for (int n = 0; n < 8; n++) { res01[n] = z; res23[n] = z; }

#pragma unroll 1
    for (int r = 0; r < 2; r++) {
        const float* x = r ? xg : xd;
        const float* Wg = r ? W1 : W0;
        const int slot = 2 * t + r;

        // Protect Wsm/Asm from the previous iteration's GEMM reads.
        __syncthreads();

        // ---- load this relation's W (L2-hot, 16 KB)
        for (int i = tid; i < 1024; i += 256)
            reinterpret_cast<float4*>(Wsm)[i] = reinterpret_cast<const float4*>(Wg)[i];

        // ---- gather + normalize into Asm: lane's 4-float chunk of a[node]
#pragma unroll 1
        for (int n = 0; n < 8; n++) {
            const int node = node0 + n;
            float4 a = make_float4(0.f, 0.f, 0.f, 0.f);
            if (node < NN) {
                const int idx = slot * NN + node;
                const int deg = __ldg(g_cnt + idx);
                const int end = __ldg(g_base + idx);
#pragma unroll 2
                for (int e = end - deg; e < end; e++) {
                    int s = __ldg(g_psrc + e);
                    float4 v = *reinterpret_cast<const float4*>(x + (size_t)s * DD + 4 * lane);
                    a.x += v.x; a.y += v.y; a.z += v.z; a.w += v.w;
                }
                const float inv = 1.f / (float)max(deg, 1);
                a.x *= inv; a.y *= inv; a.z *= inv; a.w *= inv;
            }
            *reinterpret_cast<float4*>(&Asm[group * 8 + n][4 * lane]) = a;
        }
        __syncthreads();

        // ---- mini-GEMM: res[n][c] += sum_k a[n][k] * W[k][c]
#pragma unroll
        for (int kl = 0; kl < 16; kl++) {
            unsigned long long w01[4], w23[4];
#pragma unroll
            for (int j = 0; j < 4; j++) {
                float4 w = *reinterpret_cast<const float4*>(Wsm + (4 * kl + j) * 64 + 4 * lane);
                w01[j] = pk2(w.x, w.y);
                w23[j] = pk2(w.z, w.w);
            }
#pragma unroll
            for (int n = 0; n < 8; n++) {
                float4 a4 = *reinterpret_cast<const float4*>(&Asm[group * 8 + n][4 * kl]);
#pragma unroll
                for (int j = 0; j < 4; j++) {
                    float s = (j == 0) ? a4.x : (j == 1) ? a4.y : (j == 2) ? a4.z : a4.w;
                    unsigned long long ss = pk2(s, s);
                    fma2(res01[n], ss, w01[j]);
                    fma2(res23[n], ss, w23[j]);
                }
            }
        }
    }

    // ---- bias + relu + store
    const float4 b = reinterpret_cast<const float4*>(bias)[lane];
#pragma unroll
    for (int n = 0; n < 8; n++) {
        const int node = node0 + n;
        if (node >= NN) continue;
        float2 lo = up2(res01[n]);
        float2 hi = up2(res23[n]);
        float4 o;
        o.x = fmaxf(lo.x + b.x, 0.f);
        o.y = fmaxf(lo.y + b.y, 0.f);
        o.z = fmaxf(hi.x + b.z, 0.f);
        o.w = fmaxf(hi.y + b.w, 0.f);
        *reinterpret_cast<float4*>(out + (size_t)t * NN * DD + (size_t)node * DD + 4 * lane) = o;
    }
}

// ---------------------------------------------------------------------------
extern "C" void kernel_launch(void* const* d_in, const int* in_sizes, int n_in,
                              void* d_out, int out_size) {
    const float* xd   = (const float*)d_in[0];
    const float* xg   = (const float*)d_in[1];
    const float* Wdd  = (const float*)d_in[2];
    const float* Wdg  = (const float*)d_in[3];
    const float* Wgd  = (const float*)d_in[4];
    const float* Wgg  = (const float*)d_in[5];
    const float* bias = (const float*)d_in[6];
    const int* src_dd = (const int*)d_in[7];
    const int* dst_dd = (const int*)d_in[8];
    const int* src_dg = (const int*)d_in[9];
    const int* dst_dg = (const int*)d_in[10];
    const int* src_gd = (const int*)d_in[11];
    const int* dst_gd = (const int*)d_in[12];
    const int* src_gg = (const int*)d_in[13];
    const int* dst_gg = (const int*)d_in[14];
    float* out = (float*)d_out;

    const int n_edges = in_sizes[7];  // all four relations share E
    const int eb = (n_edges + 255) / 256;

    zero_cnt_kernel<<<(TOT + 255) / 256, 256>>>();
    // slots: 0=(src_dd,dst_dd) 1=(src_gd,dst_gd) 2=(src_dg,dst_dg) 3=(src_gg,dst_gg)
    hist_kernel<<<dim3(eb, 4), 256>>>(dst_dd, dst_gd, dst_dg, dst_gg, n_edges);
    scan_blocks_kernel<<<NB, 1024>>>();
    scan_partials_kernel<<<1, 512>>>();
    add_base_kernel<<<(TOT + 255) / 256, 256>>>();
    scatter_perm_kernel<<<dim3(eb, 4), 256>>>(src_dd, dst_dd, src_gd, dst_gd,
                                              src_dg, dst_dg, src_gg, dst_gg, n_edges);
    gather_gemm_kernel<<<dim3((NN + 127) / 128, 2), 256>>>(xd, xg, Wdd, Wdg, Wgd, Wgg,
                                                           bias, out);
}

// round 12
// speedup vs baseline: 1.4135x; 1.4135x over previous
#include <cuda_runtime.h>

#define NN 100000
#define DD 64
#define EMAX 800000
#define TOT (4 * NN)              // total count slots
#define NB ((TOT + 1023) / 1024)  // scan blocks = 391

// Scratch (static device globals; no runtime allocation).
// slot layout (by dst): 0=dd(drug) 1=gd(drug) 2=dg(gene) 3=gg(gene)
__device__ int g_cnt[TOT];           // per-(slot,dst) degree
__device__ int g_incl[TOT];          // block-inclusive scan
__device__ int g_base[TOT];          // exclusive offsets; after scatter_perm = end offsets
__device__ int g_bsum[512];          // per-block totals
__device__ int g_bbase[512];         // exclusive block bases
__device__ int g_psrc[4ull * EMAX];  // src indices sorted by (slot, dst)

// ---------------------------------------------------------------------------
__global__ void zero_cnt_kernel() {
    int i = blockIdx.x * blockDim.x + threadIdx.x;
    if (i < TOT) g_cnt[i] = 0;
}

// ---------------------------------------------------------------------------
// Counting sort, step 1: per-(slot,dst) histogram. 4 edges per thread (int4).
// ---------------------------------------------------------------------------
__global__ __launch_bounds__(256) void hist_kernel(
    const int* __restrict__ dst0, const int* __restrict__ dst1,
    const int* __restrict__ dst2, const int* __restrict__ dst3,
    int n_edges) {
    const int slot = blockIdx.y;
    const int* dst = (slot == 0) ? dst0 : (slot == 1) ? dst1 : (slot == 2) ? dst2 : dst3;
    int e0 = (blockIdx.x * 256 + threadIdx.x) * 4;
    if (e0 + 3 < n_edges) {
        int4 d4 = *reinterpret_cast<const int4*>(dst + e0);
        atomicAdd(&g_cnt[slot * NN + d4.x], 1);
        atomicAdd(&g_cnt[slot * NN + d4.y], 1);
        atomicAdd(&g_cnt[slot * NN + d4.z], 1);
        atomicAdd(&g_cnt[slot * NN + d4.w], 1);
    } else {
        for (int e = e0; e < n_edges; e++)
            atomicAdd(&g_cnt[slot * NN + __ldg(dst + e)], 1);
    }
}

// ---------------------------------------------------------------------------
// Step 2a: per-block inclusive scan (1024 elems/block) + block totals.
// ---------------------------------------------------------------------------
__global__ __launch_bounds__(1024) void scan_blocks_kernel() {
    __shared__ int s[1024];
    const int tid = threadIdx.x;
    const int i = blockIdx.x * 1024 + tid;
    int v = (i < TOT) ? g_cnt[i] : 0;
    s[tid] = v;
    __syncthreads();
#pragma unroll
    for (int off = 1; off < 1024; off <<= 1) {
        int t = (tid >= off) ? s[tid - off] : 0;
        __syncthreads();
        s[tid] += t;
        __syncthreads();
    }
    if (i < TOT) g_incl[i] = s[tid];
    if (tid == 1023) g_bsum[blockIdx.x] = s[1023];
}

// Step 2b: scan the 391 block totals (single block) -> exclusive block bases.
__global__ __launch_bounds__(512) void scan_partials_kernel() {
    __shared__ int s[512];
    const int tid = threadIdx.x;
    int v = (tid < NB) ? g_bsum[tid] : 0;
    s[tid] = v;
    __syncthreads();
#pragma unroll
    for (int off = 1; off < 512; off <<= 1) {
        int t = (tid >= off) ? s[tid - off] : 0;
        __syncthreads();
        s[tid] += t;
        __syncthreads();
    }
    g_bbase[tid] = s[tid] - v;  // exclusive
}

// Step 2c: global exclusive offset per slot-index.
__global__ __launch_bounds__(256) void add_base_kernel() {
    int i = blockIdx.x * 256 + threadIdx.x;
    if (i >= TOT) return;
    g_base[i] = g_bbase[i >> 10] + g_incl[i] - g_cnt[i];
}

// ---------------------------------------------------------------------------
// Step 3: scatter src indices into dst-sorted order. Afterwards g_base[idx]
// holds the END offset of segment idx (start = end - g_cnt[idx]).
// 4 edges per thread (int4 index loads; scattered 4B writes unchanged).
// ---------------------------------------------------------------------------
__global__ __launch_bounds__(256) void scatter_perm_kernel(
    const int* __restrict__ src0, const int* __restrict__ dst0,
    const int* __restrict__ src1, const int* __restrict__ dst1,
    const int* __restrict__ src2, const int* __restrict__ dst2,
    const int* __restrict__ src3, const int* __restrict__ dst3,
    int n_edges) {
    const int slot = blockIdx.y;
    const int* src; const int* dst;
    switch (slot) {
        case 0:  src = src0; dst = dst0; break;
        case 1:  src = src1; dst = dst1; break;
        case 2:  src = src2; dst = dst2; break;
        default: src = src3; dst = dst3; break;
    }
    int e0 = (blockIdx.x * 256 + threadIdx.x) * 4;
    if (e0 + 3 < n_edges) {
        int4 s4 = *reinterpret_cast<const int4*>(src + e0);
        int4 d4 = *reinterpret_cast<const int4*>(dst + e0);
        g_psrc[atomicAdd(&g_base[slot * NN + d4.x], 1)] = s4.x;
        g_psrc[atomicAdd(&g_base[slot * NN + d4.y], 1)] = s4.y;
        g_psrc[atomicAdd(&g_base[slot * NN + d4.z], 1)] = s4.z;
        g_psrc[atomicAdd(&g_base[slot * NN + d4.w], 1)] = s4.w;
    } else {
        for (int e = e0; e < n_edges; e++) {
            int s = __ldg(src + e);
            int d = __ldg(dst + e);
            g_psrc[atomicAdd(&g_base[slot * NN + d], 1)] = s;
        }
    }
}

// ---------------------------------------------------------------------------
// f32x2 packed-FMA helpers (Blackwell).
// ---------------------------------------------------------------------------
__device__ __forceinline__ unsigned long long pk2(float lo, float hi) {
    unsigned long long r;
    asm("mov.b64 %0, {%1, %2};" : "=l"(r) : "f"(lo), "f"(hi));
    return r;
}
__device__ __forceinline__ void fma2(unsigned long long& acc,
                                     unsigned long long a, unsigned long long b) {
    asm("fma.rn.f32x2 %0, %1, %2, %0;" : "+l"(acc) : "l"(a), "l"(b));
}
__device__ __forceinline__ float2 up2(unsigned long long v) {
    float2 f;
    asm("mov.b64 {%0, %1}, %2;" : "=f"(f.x), "=f"(f.y) : "l"(v));
    return f;
}
__device__ __forceinline__ float4 shfl4(float4 v, int src) {
    float4 r;
    r.x = __shfl_sync(0xffffffffu, v.x, src, 16);
    r.y = __shfl_sync(0xffffffffu, v.y, src, 16);
    r.z = __shfl_sync(0xffffffffu, v.z, src, 16);
    r.w = __shfl_sync(0xffffffffu, v.w, src, 16);
    return r;
}

// ---------------------------------------------------------------------------
// Fused pull-gather + per-node 64x64 GEMM + bias + relu + output.
// Linearity: (sum_e x[src]) / deg @ W == GraphConv(norm='right').
// 16 lanes per node, 4 nodes per lane-group; 800K threads total (parallelism
// is load-bearing: the gather is latency-bound — do NOT reduce thread count).
// Lane l owns feature chunk [4l, 4l+4) of both the aggregate and the output.
// ---------------------------------------------------------------------------
__global__ __launch_bounds__(256) void gather_gemm_kernel(
    const float* __restrict__ xd, const float* __restrict__ xg,
    const float* __restrict__ Wdd, const float* __restrict__ Wdg,
    const float* __restrict__ Wgd, const float* __restrict__ Wgg,
    const float* __restrict__ bias, float* __restrict__ out) {
    __shared__ float Wsm[2][64 * 64];  // [rel][k*64 + c], 32 KB

    const int t = blockIdx.y;  // 0=drug dst, 1=gene dst
    const int tid = threadIdx.x;
    const int lane = tid & 15;
    const int group = tid >> 4;                     // 0..15
    const int node0 = blockIdx.x * 64 + group * 4;  // 4 nodes per group

    // rel0 src = x_drug, rel1 src = x_gene.
    //   t=0: rel0=(slot0, W_dd), rel1=(slot1, W_gd)
    //   t=1: rel0=(slot2, W_dg), rel1=(slot3, W_gg)
    const float* W0 = t ? Wdg : Wdd;
    const float* W1 = t ? Wgg : Wgd;
    for (int i = tid; i < 1024; i += 256) {
        reinterpret_cast<float4*>(Wsm[0])[i] = reinterpret_cast<const float4*>(W0)[i];
        reinterpret_cast<float4*>(Wsm[1])[i] = reinterpret_cast<const float4*>(W1)[i];
    }
    __syncthreads();

    unsigned long long res01[4], res23[4];
    const unsigned long long z = pk2(0.f, 0.f);
#pragma unroll
    for (int n = 0; n < 4; n++) { res01[n] = z; res23[n] = z; }

#pragma unroll 1
    for (int r = 0; r < 2; r++) {
        const float* x = r ? xg : xd;
        const int slot = 2 * t + r;

        // ---- gather + normalize: a[n] = (sum_e x[src]) / deg, lane's chunk
        float4 a[4];
#pragma unroll
        for (int n = 0; n < 4; n++) {
            a[n] = make_float4(0.f, 0.f, 0.f, 0.f);
            const int node = node0 + n;
            if (node >= NN) continue;
            const int idx = slot * NN + node;
            const int deg = __ldg(g_cnt + idx);
            const int end = __ldg(g_base + idx);
#pragma unroll 2
            for (int e = end - deg; e < end; e++) {
                int s = __ldg(g_psrc + e);
                float4 v = *reinterpret_cast<const float4*>(x + (size_t)s * DD + 4 * lane);
                a[n].x += v.x; a[n].y += v.y; a[n].z += v.z; a[n].w += v.w;
            }
            const float inv = 1.f / (float)max(deg, 1);
            a[n].x *= inv; a[n].y *= inv; a[n].z *= inv; a[n].w *= inv;
        }

        // ---- mini-GEMM: res[n][c] += sum_k a[n][k] * W[k][c], c = lane cols
        const float* Wr = Wsm[r];
#pragma unroll
        for (int kl = 0; kl < 16; kl++) {
            float4 av[4];
#pragma unroll
            for (int n = 0; n < 4; n++) av[n] = shfl4(a[n], kl);
#pragma unroll
            for (int j = 0; j < 4; j++) {
                const int k = 4 * kl + j;
                float4 w = *reinterpret_cast<const float4*>(Wr + k * 64 + 4 * lane);
                unsigned long long w01 = pk2(w.x, w.y);
                unsigned long long w23 = pk2(w.z, w.w);
#pragma unroll
                for (int n = 0; n < 4; n++) {
                    float s = (j == 0) ? av[n].x : (j == 1) ? av[n].y
                            : (j == 2) ? av[n].z : av[n].w;
                    unsigned long long ss = pk2(s, s);
                    fma2(res01[n], ss, w01);
                    fma2(res23[n], ss, w23);
                }
            }
        }
    }

    // ---- bias + relu + store
    const float4 b = reinterpret_cast<const float4*>(bias)[lane];
#pragma unroll
    for (int n = 0; n < 4; n++) {
        const int node = node0 + n;
        if (node >= NN) continue;
        float2 lo = up2(res01[n]);
        float2 hi = up2(res23[n]);
        float4 o;
        o.x = fmaxf(lo.x + b.x, 0.f);
        o.y = fmaxf(lo.y + b.y, 0.f);
        o.z = fmaxf(hi.x + b.z, 0.f);
        o.w = fmaxf(hi.y + b.w, 0.f);
        *reinterpret_cast<float4*>(out + (size_t)t * NN * DD + (size_t)node * DD + 4 * lane) = o;
    }
}

// ---------------------------------------------------------------------------
extern "C" void kernel_launch(void* const* d_in, const int* in_sizes, int n_in,
                              void* d_out, int out_size) {
    const float* xd   = (const float*)d_in[0];
    const float* xg   = (const float*)d_in[1];
    const float* Wdd  = (const float*)d_in[2];
    const float* Wdg  = (const float*)d_in[3];
    const float* Wgd  = (const float*)d_in[4];
    const float* Wgg  = (const float*)d_in[5];
    const float* bias = (const float*)d_in[6];
    const int* src_dd = (const int*)d_in[7];
    const int* dst_dd = (const int*)d_in[8];
    const int* src_dg = (const int*)d_in[9];
    const int* dst_dg = (const int*)d_in[10];
    const int* src_gd = (const int*)d_in[11];
    const int* dst_gd = (const int*)d_in[12];
    const int* src_gg = (const int*)d_in[13];
    const int* dst_gg = (const int*)d_in[14];
    float* out = (float*)d_out;

    const int n_edges = in_sizes[7];  // all four relations share E
    const int eb4 = (n_edges / 4 + 255) / 256;  // 4 edges per thread

    zero_cnt_kernel<<<(TOT + 255) / 256, 256>>>();
    // slots: 0=(src_dd,dst_dd) 1=(src_gd,dst_gd) 2=(src_dg,dst_dg) 3=(src_gg,dst_gg)
    hist_kernel<<<dim3(eb4, 4), 256>>>(dst_dd, dst_gd, dst_dg, dst_gg, n_edges);
    scan_blocks_kernel<<<NB, 1024>>>();
    scan_partials_kernel<<<1, 512>>>();
    add_base_kernel<<<(TOT + 255) / 256, 256>>>();
    scatter_perm_kernel<<<dim3(eb4, 4), 256>>>(src_dd, dst_dd, src_gd, dst_gd,
                                               src_dg, dst_dg, src_gg, dst_gg, n_edges);
    gather_gemm_kernel<<<dim3((NN + 63) / 64, 2), 256>>>(xd, xg, Wdd, Wdg, Wgd, Wgg,
                                                         bias, out);
}